// round 8
// baseline (speedup 1.0000x reference)
#include <cuda_runtime.h>
#include <cuda_bf16.h>
#include <math.h>
#include <stdint.h>

#define N 8192
#define D 128
#define NC 512
#define MAXM 64

// ---------------- scratch (device globals; no allocation allowed) ----------
__device__ __align__(16) float g_enorm[N * D];
__device__ __align__(16) signed char g_qa[N * D];   // round(x*128)
__device__ __align__(16) signed char g_qb[N * D];   // round((x-a/128)*2^14)
__device__ int   g_cnt[NC];
__device__ int   g_members[NC * MAXM];
__device__ float g_lsep[N];
__device__ float g_samesum[N];
__device__ float g_sall[N];
__device__ float g_part[32];
__device__ int   g_pcnt[32];
__device__ int   g_is64;

__device__ __forceinline__ float an_exp(float s) {
    float t = fmaxf(s + 0.4f, 0.0f);
    return __expf(80.0f * t * (s - 0.4f));
}

__device__ __forceinline__ int get_label(const void* lab, int i) {
    if (g_is64) return (int)((const long long*)lab)[i];
    return ((const int*)lab)[i];
}

__device__ __forceinline__ uint32_t smem_u32(const void* p) {
    uint32_t a;
    asm("{ .reg .u64 t; cvta.to.shared.u64 t, %1; cvt.u32.u64 %0, t; }" : "=r"(a) : "l"(p));
    return a;
}
__device__ __forceinline__ void cpa16(uint32_t dst, const void* src) {
    asm volatile("cp.async.cg.shared.global [%0], [%1], 16;" :: "r"(dst), "l"(src) : "memory");
}
__device__ __forceinline__ void ldsm4(uint32_t* r, uint32_t addr) {
    asm volatile("ldmatrix.sync.aligned.m8n8.x4.shared.b16 {%0,%1,%2,%3}, [%4];"
        : "=r"(r[0]), "=r"(r[1]), "=r"(r[2]), "=r"(r[3]) : "r"(addr));
}
__device__ __forceinline__ void mma_s8(int* d, const uint32_t* a, uint32_t b0, uint32_t b1) {
    asm volatile(
        "mma.sync.aligned.m16n8k32.row.col.s32.s8.s8.s32 "
        "{%0,%1,%2,%3}, {%4,%5,%6,%7}, {%8,%9}, {%0,%1,%2,%3};\n"
        : "+r"(d[0]), "+r"(d[1]), "+r"(d[2]), "+r"(d[3])
        : "r"(a[0]), "r"(a[1]), "r"(a[2]), "r"(a[3]), "r"(b0), "r"(b1));
}

// ---------------- kernel 0: tiny pre (g_cnt zero + dtype flag) -------------
__global__ void k_pre(const void* lab) {
    int i = blockIdx.x * blockDim.x + threadIdx.x;
    if (i < NC) g_cnt[i] = 0;
    if (i == 0) {
        const int* w = (const int*)lab;
        int bad = 0;
        #pragma unroll
        for (int k = 1; k < 128; k += 2) bad |= w[k];
        g_is64 = (bad == 0);
    }
}

// ---------------- kernel 1: normalize + int8 2-limb quant + class lists ----
__global__ void k_norm(const float* __restrict__ in, const void* __restrict__ lab) {
    int gid = blockIdx.x * blockDim.x + threadIdx.x;
    if (gid < N) g_sall[gid] = 0.0f;
    int row  = blockIdx.x * 8 + (threadIdx.x >> 5);
    int lane = threadIdx.x & 31;
    float4 v = *(const float4*)(in + row * D + lane * 4);
    float ss = v.x * v.x + v.y * v.y + v.z * v.z + v.w * v.w;
    #pragma unroll
    for (int m = 16; m >= 1; m >>= 1) ss += __shfl_xor_sync(0xffffffffu, ss, m);
    float inv = 1.0f / fmaxf(sqrtf(ss), 1e-12f);
    float o[4] = {v.x * inv, v.y * inv, v.z * inv, v.w * inv};
    float4 of; of.x = o[0]; of.y = o[1]; of.z = o[2]; of.w = o[3];
    *(float4*)(g_enorm + row * D + lane * 4) = of;
    char4 qa, qb;
    signed char qav[4], qbv[4];
    #pragma unroll
    for (int c = 0; c < 4; c++) {
        float af = rintf(o[c] * 128.0f);
        af = fminf(fmaxf(af, -127.0f), 127.0f);
        float r = o[c] - af * 0.0078125f;           // x - a*2^-7
        float bf = rintf(r * 16384.0f);             // * 2^14
        bf = fminf(fmaxf(bf, -127.0f), 127.0f);
        qav[c] = (signed char)(int)af;
        qbv[c] = (signed char)(int)bf;
    }
    qa.x = qav[0]; qa.y = qav[1]; qa.z = qav[2]; qa.w = qav[3];
    qb.x = qbv[0]; qb.y = qbv[1]; qb.z = qbv[2]; qb.w = qbv[3];
    *(char4*)(g_qa + row * D + lane * 4) = qa;
    *(char4*)(g_qb + row * D + lane * 4) = qb;
    if (lane == 0) {
        int c = get_label(lab, row);
        int p = atomicAdd(&g_cnt[c], 1);
        if (p < MAXM) g_members[c * MAXM + p] = row;
    }
}

// ---------------- kernel 2: per-class positives, warp-per-anchor -----------
__global__ void k_class() {
    int c = blockIdx.x;
    __shared__ int   mlist[MAXM];
    __shared__ float se[MAXM * 129];
    int m = g_cnt[c];
    if (m > MAXM) m = MAXM;
    if (m == 0) return;
    int tid = threadIdx.x, lane = tid & 31, wid = tid >> 5;
    if (tid < m) mlist[tid] = g_members[c * MAXM + tid];
    __syncthreads();
    for (int p = tid; p < m * D; p += blockDim.x) {
        int r = p >> 7, k = p & 127;
        se[r * 129 + k] = g_enorm[mlist[r] * D + k];
    }
    __syncthreads();
    for (int a = wid; a < m; a += 4) {
        int b0 = lane, b1 = lane + 32;
        float s0 = 0.0f, s1 = 0.0f;
        const float* ra = se + a * 129;
        #pragma unroll 8
        for (int k = 0; k < D; k++) {
            float av = ra[k];
            s0 = fmaf(av, se[b0 * 129 + k], s0);
            s1 = fmaf(av, se[b1 * 129 + k], s1);
        }
        float ap0 = -1e30f, ap1 = -1e30f, an0 = 0.0f, an1 = 0.0f;
        bool v0 = (b0 < m && b0 != a), v1 = (b1 < m && b1 != a);
        if (v0) { ap0 = -80.0f * fmaxf(1.4f - s0, 0.0f) * (s0 - 0.6f); an0 = an_exp(s0); }
        if (v1) { ap1 = -80.0f * fmaxf(1.4f - s1, 0.0f) * (s1 - 0.6f); an1 = an_exp(s1); }
        float mx = fmaxf(ap0, ap1);
        #pragma unroll
        for (int k = 16; k >= 1; k >>= 1) mx = fmaxf(mx, __shfl_xor_sync(0xffffffffu, mx, k));
        float es = (v0 ? __expf(ap0 - mx) : 0.0f) + (v1 ? __expf(ap1 - mx) : 0.0f);
        float sa = an0 + an1;
        #pragma unroll
        for (int k = 16; k >= 1; k >>= 1) {
            es += __shfl_xor_sync(0xffffffffu, es, k);
            sa += __shfl_xor_sync(0xffffffffu, sa, k);
        }
        if (lane == 0) {
            g_lsep[mlist[a]]    = mx + logf(es);
            g_samesum[mlist[a]] = sa;
        }
    }
}

// ---------------- kernel 3: int8 IMMA GEMM + fused an-sumexp ---------------
// smem: 4 arrays (Aa, Ab, Ba, Bb), each 128 rows x 128 int8, stride 144B.
// ldmatrix 16B rows: banks (36g mod 32 = 4g) distinct -> conflict-free.
// K=128 int8 fully resident: single load phase, 4 k-chunks of 32.
#define SROW   144
#define ARR    (128 * SROW)      // 18432 B
#define SMEM_SZ (4 * ARR)        // 73728 B

__global__ void __launch_bounds__(256) k_main_i() {
    int b = blockIdx.x;
    int r = (int)((__fsqrt_rn(8.0f * (float)b + 1.0f) - 1.0f) * 0.5f);
    while ((r + 1) * (r + 2) / 2 <= b) r++;
    while (r * (r + 1) / 2 > b) r--;
    int bi = b - r * (r + 1) / 2;
    int bj = r;

    extern __shared__ char sm[];
    uint32_t sb = smem_u32(sm);
    int tid = threadIdx.x;
    int lane = tid & 31, wid = tid >> 5;
    int g = lane >> 2, t = lane & 3;
    int wm = wid & 3, wn = wid >> 2;             // 4x2 warps, warp tile 32x64
    int rowBase = bi * 128, colBase = bj * 128;

    // ---- load all 4 arrays (64 KB total) via cp.async ----
    #pragma unroll
    for (int it = 0; it < 4; it++) {
        int idx = it * 256 + tid;                // 0..1023 per array
        int row = idx >> 3, k8 = idx & 7;
        uint32_t so = (uint32_t)(row * SROW + k8 * 16);
        const uint4* A = (const uint4*)g_qa + (size_t)(rowBase + row) * 8 + k8;
        const uint4* Bq = (const uint4*)g_qb + (size_t)(rowBase + row) * 8 + k8;
        const uint4* C = (const uint4*)g_qa + (size_t)(colBase + row) * 8 + k8;
        const uint4* Dq = (const uint4*)g_qb + (size_t)(colBase + row) * 8 + k8;
        cpa16(sb + 0 * ARR + so, A);
        cpa16(sb + 1 * ARR + so, Bq);
        cpa16(sb + 2 * ARR + so, C);
        cpa16(sb + 3 * ARR + so, Dq);
    }
    asm volatile("cp.async.commit_group;" ::: "memory");
    asm volatile("cp.async.wait_group 0;" ::: "memory");
    __syncthreads();

    uint32_t lmo = (uint32_t)((lane & 15) * SROW + (lane >> 4) * 16);
    uint32_t wmoff = (uint32_t)(wm * 32) * SROW;
    uint32_t wnoff = (uint32_t)(wn * 64) * SROW;

    float simacc[2][8][4];
    #pragma unroll
    for (int i = 0; i < 2; i++)
        #pragma unroll
        for (int j = 0; j < 8; j++)
            #pragma unroll
            for (int e = 0; e < 4; e++) simacc[i][j][e] = 0.0f;

    int work[2][8][4];

    #define ZERO_WORK() do {                                                   \
        _Pragma("unroll")                                                      \
        for (int i = 0; i < 2; i++)                                            \
            _Pragma("unroll")                                                  \
            for (int j = 0; j < 8; j++)                                        \
                _Pragma("unroll")                                              \
                for (int e = 0; e < 4; e++) work[i][j][e] = 0;                 \
    } while (0)

    #define FOLD(scale) do {                                                   \
        _Pragma("unroll")                                                      \
        for (int i = 0; i < 2; i++)                                            \
            _Pragma("unroll")                                                  \
            for (int j = 0; j < 8; j++)                                        \
                _Pragma("unroll")                                              \
                for (int e = 0; e < 4; e++)                                    \
                    simacc[i][j][e] += (float)work[i][j][e] * (scale);         \
    } while (0)

    #define SWEEP(AOFF, BOFF) do {                                             \
        _Pragma("unroll")                                                      \
        for (int kc = 0; kc < 4; kc++) {                                       \
            uint32_t ko = (uint32_t)(kc * 32);                                 \
            uint32_t a0[4], a1[4];                                             \
            ldsm4(a0, sb + (AOFF) + wmoff + lmo + ko);                         \
            ldsm4(a1, sb + (AOFF) + wmoff + lmo + ko + 16 * SROW);             \
            _Pragma("unroll")                                                  \
            for (int jp = 0; jp < 4; jp++) {                                   \
                uint32_t bq[4];                                                \
                ldsm4(bq, sb + (BOFF) + wnoff + lmo + ko                       \
                          + (uint32_t)(jp * 16) * SROW);                       \
                mma_s8(work[0][2 * jp],     a0, bq[0], bq[2]);                 \
                mma_s8(work[1][2 * jp],     a1, bq[0], bq[2]);                 \
                mma_s8(work[0][2 * jp + 1], a0, bq[1], bq[3]);                 \
                mma_s8(work[1][2 * jp + 1], a1, bq[1], bq[3]);                 \
            }                                                                  \
        }                                                                      \
    } while (0)

    // product 1: a.a'  (scale 2^-14)
    ZERO_WORK();
    SWEEP(0 * ARR, 2 * ARR);
    FOLD(6.103515625e-05f);
    // product 2: a.b' + b.a'  (scale 2^-21)
    ZERO_WORK();
    SWEEP(0 * ARR, 3 * ARR);
    SWEEP(1 * ARR, 2 * ARR);
    FOLD(4.76837158203125e-07f);
    // product 3: b.b'  (scale 2^-28)
    ZERO_WORK();
    SWEEP(1 * ARR, 3 * ARR);
    FOLD(3.725290298461914e-09f);

    #undef SWEEP
    #undef FOLD
    #undef ZERO_WORK

    bool diag = (bi == bj);
    #pragma unroll
    for (int i = 0; i < 2; i++)
        #pragma unroll
        for (int j = 0; j < 8; j++)
            #pragma unroll
            for (int e = 0; e < 4; e++) {
                float x = an_exp(simacc[i][j][e]);
                if (diag) {
                    int rl = wm * 32 + i * 16 + g + ((e >> 1) << 3);
                    int cl = wn * 64 + j * 8 + 2 * t + (e & 1);
                    if (rl == cl) x = 0.0f;
                }
                simacc[i][j][e] = x;
            }
    // row sums
    #pragma unroll
    for (int i = 0; i < 2; i++)
        #pragma unroll
        for (int h = 0; h < 2; h++) {
            float v = 0.0f;
            #pragma unroll
            for (int j = 0; j < 8; j++) v += simacc[i][j][2 * h] + simacc[i][j][2 * h + 1];
            v += __shfl_xor_sync(0xffffffffu, v, 1);
            v += __shfl_xor_sync(0xffffffffu, v, 2);
            if (t == 0)
                atomicAdd(&g_sall[rowBase + wm * 32 + i * 16 + g + h * 8], v);
        }
    // col sums (only off-diagonal tiles)
    if (!diag) {
        #pragma unroll
        for (int j = 0; j < 8; j++)
            #pragma unroll
            for (int bb = 0; bb < 2; bb++) {
                float v = simacc[0][j][bb] + simacc[0][j][2 + bb] +
                          simacc[1][j][bb] + simacc[1][j][2 + bb];
                v += __shfl_xor_sync(0xffffffffu, v, 4);
                v += __shfl_xor_sync(0xffffffffu, v, 8);
                v += __shfl_xor_sync(0xffffffffu, v, 16);
                if (g == 0)
                    atomicAdd(&g_sall[colBase + wn * 64 + j * 8 + 2 * t + bb], v);
            }
    }
}

// ---------------- kernel 4a: parallel finalize (one anchor per thread) -----
__global__ void k_finalp(const void* __restrict__ lab) {
    __shared__ float ssum[256];
    __shared__ int   scnt[256];
    int tid = threadIdx.x;
    int i = blockIdx.x * 256 + tid;
    int c = get_label(lab, i);
    int m = g_cnt[c];
    int np = m - 1, nn = N - m;
    float sp = 0.0f;
    int ok = 0;
    if (np > 0 && nn > 0) {
        float sneg = g_sall[i] - g_samesum[i];
        sneg = fmaxf(sneg, 1e-30f);
        float x = g_lsep[i] + logf((float)nn) + logf(sneg) + logf((float)np);
        sp = (x > 0.0f) ? (x + log1pf(__expf(-x))) : log1pf(__expf(x));
        ok = 1;
    }
    ssum[tid] = sp; scnt[tid] = ok;
    __syncthreads();
    #pragma unroll
    for (int s = 128; s > 0; s >>= 1) {
        if (tid < s) { ssum[tid] += ssum[tid + s]; scnt[tid] += scnt[tid + s]; }
        __syncthreads();
    }
    if (tid == 0) { g_part[blockIdx.x] = ssum[0]; g_pcnt[blockIdx.x] = scnt[0]; }
}

// ---------------- kernel 4b: deterministic 32-way reduce -------------------
__global__ void k_final2(float* __restrict__ out) {
    int lane = threadIdx.x;
    float v = g_part[lane];
    int   c = g_pcnt[lane];
    #pragma unroll
    for (int k = 16; k >= 1; k >>= 1) {
        v += __shfl_xor_sync(0xffffffffu, v, k);
        c += __shfl_xor_sync(0xffffffffu, c, k);
    }
    if (lane == 0) out[0] = v / fmaxf((float)c, 1.0f);
}

// ---------------- launch ---------------------------------------------------
extern "C" void kernel_launch(void* const* d_in, const int* in_sizes, int n_in,
                              void* d_out, int out_size) {
    const float* embeds = (const float*)d_in[0];
    const void*  labels = d_in[1];
    float* out = (float*)d_out;
    (void)in_sizes; (void)n_in; (void)out_size;

    cudaFuncSetAttribute(k_main_i, cudaFuncAttributeMaxDynamicSharedMemorySize, SMEM_SZ);

    k_pre<<<2, 256>>>(labels);
    k_norm<<<N / 8, 256>>>(embeds, labels);
    k_class<<<NC, 128>>>();
    k_main_i<<<2080, 256, SMEM_SZ>>>();
    k_finalp<<<32, 256>>>(labels);
    k_final2<<<1, 32>>>(out);
}

// round 9
// speedup vs baseline: 4.6223x; 4.6223x over previous
#include <cuda_runtime.h>
#include <cuda_fp16.h>
#include <math.h>
#include <stdint.h>

#define N 8192
#define D 128
#define NC 512
#define MAXM 64

// ---------------- scratch (device globals; no allocation allowed) ----------
__device__ __align__(16) float g_enorm[N * D];
__device__ __align__(16) __half g_h16[N * D];   // fp16(x)
__device__ __align__(16) __half g_m16[N * D];   // fp16(x - h)
__device__ int   g_cnt[NC];
__device__ int   g_members[NC * MAXM];
__device__ float g_lsep[N];
__device__ float g_samesum[N];
__device__ float g_sall[N];
__device__ float g_part[32];
__device__ int   g_pcnt[32];
__device__ int   g_is64;

__device__ __forceinline__ float an_exp(float s) {
    float t = fmaxf(s + 0.4f, 0.0f);
    return __expf(80.0f * t * (s - 0.4f));
}

__device__ __forceinline__ int get_label(const void* lab, int i) {
    if (g_is64) return (int)((const long long*)lab)[i];
    return ((const int*)lab)[i];
}

__device__ __forceinline__ uint32_t smem_u32(const void* p) {
    uint32_t a;
    asm("{ .reg .u64 t; cvta.to.shared.u64 t, %1; cvt.u32.u64 %0, t; }" : "=r"(a) : "l"(p));
    return a;
}
__device__ __forceinline__ void cpa16(uint32_t dst, const void* src) {
    asm volatile("cp.async.cg.shared.global [%0], [%1], 16;" :: "r"(dst), "l"(src) : "memory");
}
__device__ __forceinline__ void ldsm4(uint32_t* r, uint32_t addr) {
    asm volatile("ldmatrix.sync.aligned.m8n8.x4.shared.b16 {%0,%1,%2,%3}, [%4];"
        : "=r"(r[0]), "=r"(r[1]), "=r"(r[2]), "=r"(r[3]) : "r"(addr));
}
__device__ __forceinline__ void mma_f16(float* d, const uint32_t* a, uint32_t b0, uint32_t b1) {
    asm volatile(
        "mma.sync.aligned.m16n8k16.row.col.f32.f16.f16.f32 "
        "{%0,%1,%2,%3}, {%4,%5,%6,%7}, {%8,%9}, {%0,%1,%2,%3};\n"
        : "+f"(d[0]), "+f"(d[1]), "+f"(d[2]), "+f"(d[3])
        : "r"(a[0]), "r"(a[1]), "r"(a[2]), "r"(a[3]), "r"(b0), "r"(b1));
}

// ---------------- kernel 0: tiny pre (g_cnt zero + dtype flag) -------------
__global__ void k_pre(const void* lab) {
    int i = blockIdx.x * blockDim.x + threadIdx.x;
    if (i < NC) g_cnt[i] = 0;
    if (i == 0) {
        const int* w = (const int*)lab;
        int bad = 0;
        #pragma unroll
        for (int k = 1; k < 128; k += 2) bad |= w[k];
        g_is64 = (bad == 0);
    }
}

// ---------------- kernel 1: normalize + fp16 split + class lists -----------
__global__ void k_norm(const float* __restrict__ in, const void* __restrict__ lab) {
    int gid = blockIdx.x * blockDim.x + threadIdx.x;
    if (gid < N) g_sall[gid] = 0.0f;
    int row  = blockIdx.x * 8 + (threadIdx.x >> 5);
    int lane = threadIdx.x & 31;
    float4 v = *(const float4*)(in + row * D + lane * 4);
    float ss = v.x * v.x + v.y * v.y + v.z * v.z + v.w * v.w;
    #pragma unroll
    for (int m = 16; m >= 1; m >>= 1) ss += __shfl_xor_sync(0xffffffffu, ss, m);
    float inv = 1.0f / fmaxf(sqrtf(ss), 1e-12f);
    float o[4] = {v.x * inv, v.y * inv, v.z * inv, v.w * inv};
    float4 of; of.x = o[0]; of.y = o[1]; of.z = o[2]; of.w = o[3];
    *(float4*)(g_enorm + row * D + lane * 4) = of;
    #pragma unroll
    for (int c = 0; c < 4; c++) {
        __half h = __float2half_rn(o[c]);
        float r = o[c] - __half2float(h);
        g_h16[row * D + lane * 4 + c] = h;
        g_m16[row * D + lane * 4 + c] = __float2half_rn(r);
    }
    if (lane == 0) {
        int c = get_label(lab, row);
        int p = atomicAdd(&g_cnt[c], 1);
        if (p < MAXM) g_members[c * MAXM + p] = row;
    }
}

// ---------------- kernel 2: per-class positives, warp-per-anchor (exact) ---
__global__ void k_class() {
    int c = blockIdx.x;
    __shared__ int   mlist[MAXM];
    __shared__ float se[MAXM * 129];
    int m = g_cnt[c];
    if (m > MAXM) m = MAXM;
    if (m == 0) return;
    int tid = threadIdx.x, lane = tid & 31, wid = tid >> 5;
    if (tid < m) mlist[tid] = g_members[c * MAXM + tid];
    __syncthreads();
    for (int p = tid; p < m * D; p += blockDim.x) {
        int r = p >> 7, k = p & 127;
        se[r * 129 + k] = g_enorm[mlist[r] * D + k];
    }
    __syncthreads();
    for (int a = wid; a < m; a += 4) {
        int b0 = lane, b1 = lane + 32;
        float s0 = 0.0f, s1 = 0.0f;
        const float* ra = se + a * 129;
        #pragma unroll 8
        for (int k = 0; k < D; k++) {
            float av = ra[k];
            s0 = fmaf(av, se[b0 * 129 + k], s0);
            s1 = fmaf(av, se[b1 * 129 + k], s1);
        }
        float ap0 = -1e30f, ap1 = -1e30f, an0 = 0.0f, an1 = 0.0f;
        bool v0 = (b0 < m && b0 != a), v1 = (b1 < m && b1 != a);
        if (v0) { ap0 = -80.0f * fmaxf(1.4f - s0, 0.0f) * (s0 - 0.6f); an0 = an_exp(s0); }
        if (v1) { ap1 = -80.0f * fmaxf(1.4f - s1, 0.0f) * (s1 - 0.6f); an1 = an_exp(s1); }
        float mx = fmaxf(ap0, ap1);
        #pragma unroll
        for (int k = 16; k >= 1; k >>= 1) mx = fmaxf(mx, __shfl_xor_sync(0xffffffffu, mx, k));
        float es = (v0 ? __expf(ap0 - mx) : 0.0f) + (v1 ? __expf(ap1 - mx) : 0.0f);
        float sa = an0 + an1;
        #pragma unroll
        for (int k = 16; k >= 1; k >>= 1) {
            es += __shfl_xor_sync(0xffffffffu, es, k);
            sa += __shfl_xor_sync(0xffffffffu, sa, k);
        }
        if (lane == 0) {
            g_lsep[mlist[a]]    = mx + logf(es);
            g_samesum[mlist[a]] = sa;
        }
    }
}

// -------- kernel 3: 2-product fp16 mma.sync GEMM + fused an-sumexp ---------
// Exact R6 structure, 3 smem arrays: A_h, A_m (row side), B_h (col side).
// sim = h_i.h_j + m_i.h_j  (A-side exact fp16 split, B-side fp16 only)
#define SROW   144
#define SA_H   0
#define SA_M   (128 * SROW)
#define SB_H   (2 * 128 * SROW)
#define SMEM_SZ (3 * 128 * SROW)   // 55296 B

__global__ void __launch_bounds__(256, 2) k_main_m() {
    int b = blockIdx.x;
    int r = (int)((__fsqrt_rn(8.0f * (float)b + 1.0f) - 1.0f) * 0.5f);
    while ((r + 1) * (r + 2) / 2 <= b) r++;
    while (r * (r + 1) / 2 > b) r--;
    int bi = b - r * (r + 1) / 2;
    int bj = r;

    extern __shared__ char sm[];
    uint32_t sb = smem_u32(sm);
    int tid = threadIdx.x;
    int lane = tid & 31, wid = tid >> 5;
    int g = lane >> 2, t = lane & 3;
    int wm = wid & 3, wn = wid >> 2;
    int rowBase = bi * 128, colBase = bj * 128;

    uint32_t lmo = (uint32_t)((lane & 15) * SROW + (lane >> 4) * 16);
    uint32_t aBaseH = sb + SA_H + (uint32_t)(wm * 32) * SROW + lmo;
    uint32_t aBaseM = sb + SA_M + (uint32_t)(wm * 32) * SROW + lmo;
    uint32_t bBaseH = sb + SB_H + (uint32_t)(wn * 64) * SROW + lmo;

    float acc[2][8][4];
    #pragma unroll
    for (int i = 0; i < 2; i++)
        #pragma unroll
        for (int j = 0; j < 8; j++)
            #pragma unroll
            for (int e = 0; e < 4; e++) acc[i][j][e] = 0.0f;

    for (int kc = 0; kc < 2; kc++) {
        #pragma unroll
        for (int it = 0; it < 4; it++) {
            int idx = it * 256 + tid;
            int row = idx >> 3, k8 = idx & 7;
            uint32_t so = (uint32_t)(row * SROW + k8 * 16);
            size_t gA = (size_t)(rowBase + row) * 16 + kc * 8 + k8;
            size_t gB = (size_t)(colBase + row) * 16 + kc * 8 + k8;
            cpa16(sb + SA_H + so, (const uint4*)g_h16 + gA);
            cpa16(sb + SA_M + so, (const uint4*)g_m16 + gA);
            cpa16(sb + SB_H + so, (const uint4*)g_h16 + gB);
        }
        asm volatile("cp.async.commit_group;" ::: "memory");
        asm volatile("cp.async.wait_group 0;" ::: "memory");
        __syncthreads();

        #pragma unroll
        for (int ks = 0; ks < 4; ks++) {
            uint32_t ko = (uint32_t)(ks * 32);
            uint32_t ah[2][4], am[2][4];
            ldsm4(ah[0], aBaseH + ko);
            ldsm4(ah[1], aBaseH + ko + 16 * SROW);
            ldsm4(am[0], aBaseM + ko);
            ldsm4(am[1], aBaseM + ko + 16 * SROW);
            #pragma unroll
            for (int jp = 0; jp < 4; jp++) {
                uint32_t bh[4];
                ldsm4(bh, bBaseH + ko + (uint32_t)(jp * 16) * SROW);
                mma_f16(acc[0][2 * jp],     ah[0], bh[0], bh[2]);
                mma_f16(acc[1][2 * jp],     ah[1], bh[0], bh[2]);
                mma_f16(acc[0][2 * jp + 1], ah[0], bh[1], bh[3]);
                mma_f16(acc[1][2 * jp + 1], ah[1], bh[1], bh[3]);
                mma_f16(acc[0][2 * jp],     am[0], bh[0], bh[2]);
                mma_f16(acc[1][2 * jp],     am[1], bh[0], bh[2]);
                mma_f16(acc[0][2 * jp + 1], am[0], bh[1], bh[3]);
                mma_f16(acc[1][2 * jp + 1], am[1], bh[1], bh[3]);
            }
        }
        __syncthreads();
    }

    bool diag = (bi == bj);
    #pragma unroll
    for (int i = 0; i < 2; i++)
        #pragma unroll
        for (int j = 0; j < 8; j++)
            #pragma unroll
            for (int e = 0; e < 4; e++) {
                float x = an_exp(acc[i][j][e]);
                if (diag) {
                    int rl = wm * 32 + i * 16 + g + ((e >> 1) << 3);
                    int cl = wn * 64 + j * 8 + 2 * t + (e & 1);
                    if (rl == cl) x = 0.0f;
                }
                acc[i][j][e] = x;
            }
    // row sums
    #pragma unroll
    for (int i = 0; i < 2; i++)
        #pragma unroll
        for (int h = 0; h < 2; h++) {
            float v = 0.0f;
            #pragma unroll
            for (int j = 0; j < 8; j++) v += acc[i][j][2 * h] + acc[i][j][2 * h + 1];
            v += __shfl_xor_sync(0xffffffffu, v, 1);
            v += __shfl_xor_sync(0xffffffffu, v, 2);
            if (t == 0)
                atomicAdd(&g_sall[rowBase + wm * 32 + i * 16 + g + h * 8], v);
        }
    // col sums (only off-diagonal tiles)
    if (!diag) {
        #pragma unroll
        for (int j = 0; j < 8; j++)
            #pragma unroll
            for (int bb = 0; bb < 2; bb++) {
                float v = acc[0][j][bb] + acc[0][j][2 + bb] +
                          acc[1][j][bb] + acc[1][j][2 + bb];
                v += __shfl_xor_sync(0xffffffffu, v, 4);
                v += __shfl_xor_sync(0xffffffffu, v, 8);
                v += __shfl_xor_sync(0xffffffffu, v, 16);
                if (g == 0)
                    atomicAdd(&g_sall[colBase + wn * 64 + j * 8 + 2 * t + bb], v);
            }
    }
}

// ---------------- kernel 4a: parallel finalize (one anchor per thread) -----
__global__ void k_finalp(const void* __restrict__ lab) {
    __shared__ float ssum[256];
    __shared__ int   scnt[256];
    int tid = threadIdx.x;
    int i = blockIdx.x * 256 + tid;
    int c = get_label(lab, i);
    int m = g_cnt[c];
    int np = m - 1, nn = N - m;
    float sp = 0.0f;
    int ok = 0;
    if (np > 0 && nn > 0) {
        float sneg = g_sall[i] - g_samesum[i];
        sneg = fmaxf(sneg, 1e-30f);
        float x = g_lsep[i] + logf((float)nn) + logf(sneg) + logf((float)np);
        sp = (x > 0.0f) ? (x + log1pf(__expf(-x))) : log1pf(__expf(x));
        ok = 1;
    }
    ssum[tid] = sp; scnt[tid] = ok;
    __syncthreads();
    #pragma unroll
    for (int s = 128; s > 0; s >>= 1) {
        if (tid < s) { ssum[tid] += ssum[tid + s]; scnt[tid] += scnt[tid + s]; }
        __syncthreads();
    }
    if (tid == 0) { g_part[blockIdx.x] = ssum[0]; g_pcnt[blockIdx.x] = scnt[0]; }
}

// ---------------- kernel 4b: deterministic 32-way reduce -------------------
__global__ void k_final2(float* __restrict__ out) {
    int lane = threadIdx.x;
    float v = g_part[lane];
    int   c = g_pcnt[lane];
    #pragma unroll
    for (int k = 16; k >= 1; k >>= 1) {
        v += __shfl_xor_sync(0xffffffffu, v, k);
        c += __shfl_xor_sync(0xffffffffu, c, k);
    }
    if (lane == 0) out[0] = v / fmaxf((float)c, 1.0f);
}

// ---------------- launch ---------------------------------------------------
extern "C" void kernel_launch(void* const* d_in, const int* in_sizes, int n_in,
                              void* d_out, int out_size) {
    const float* embeds = (const float*)d_in[0];
    const void*  labels = d_in[1];
    float* out = (float*)d_out;
    (void)in_sizes; (void)n_in; (void)out_size;

    cudaFuncSetAttribute(k_main_m, cudaFuncAttributeMaxDynamicSharedMemorySize, SMEM_SZ);

    k_pre<<<2, 256>>>(labels);
    k_norm<<<N / 8, 256>>>(embeds, labels);
    k_class<<<NC, 128>>>();
    k_main_m<<<2080, 256, SMEM_SZ>>>();
    k_finalp<<<32, 256>>>(labels);
    k_final2<<<1, 32>>>(out);
}

// round 10
// speedup vs baseline: 5.6412x; 1.2204x over previous
#include <cuda_runtime.h>
#include <cuda_fp16.h>
#include <math.h>
#include <stdint.h>

#define N 8192
#define D 128
#define NC 512
#define MAXM 64

// ---------------- scratch (device globals; no allocation allowed) ----------
__device__ __align__(16) float g_enorm[N * D];
__device__ __align__(16) __half g_h16[N * D];   // fp16(x)
__device__ int   g_cnt[NC];
__device__ int   g_members[NC * MAXM];
__device__ float g_lsep[N];
__device__ float g_samesum[N];
__device__ float g_sall[N];
__device__ float g_part[32];
__device__ int   g_pcnt[32];
__device__ int   g_is64;

__device__ __forceinline__ float an_exp(float s) {
    float t = fmaxf(s + 0.4f, 0.0f);
    return __expf(80.0f * t * (s - 0.4f));
}

__device__ __forceinline__ int get_label(const void* lab, int i) {
    if (g_is64) return (int)((const long long*)lab)[i];
    return ((const int*)lab)[i];
}

__device__ __forceinline__ uint32_t smem_u32(const void* p) {
    uint32_t a;
    asm("{ .reg .u64 t; cvta.to.shared.u64 t, %1; cvt.u32.u64 %0, t; }" : "=r"(a) : "l"(p));
    return a;
}
__device__ __forceinline__ void cpa16(uint32_t dst, const void* src) {
    asm volatile("cp.async.cg.shared.global [%0], [%1], 16;" :: "r"(dst), "l"(src) : "memory");
}
__device__ __forceinline__ void ldsm4(uint32_t* r, uint32_t addr) {
    asm volatile("ldmatrix.sync.aligned.m8n8.x4.shared.b16 {%0,%1,%2,%3}, [%4];"
        : "=r"(r[0]), "=r"(r[1]), "=r"(r[2]), "=r"(r[3]) : "r"(addr));
}
__device__ __forceinline__ void mma_f16(float* d, const uint32_t* a, uint32_t b0, uint32_t b1) {
    asm volatile(
        "mma.sync.aligned.m16n8k16.row.col.f32.f16.f16.f32 "
        "{%0,%1,%2,%3}, {%4,%5,%6,%7}, {%8,%9}, {%0,%1,%2,%3};\n"
        : "+f"(d[0]), "+f"(d[1]), "+f"(d[2]), "+f"(d[3])
        : "r"(a[0]), "r"(a[1]), "r"(a[2]), "r"(a[3]), "r"(b0), "r"(b1));
}

// ---------------- kernel 0: tiny pre (g_cnt zero + dtype flag) -------------
__global__ void k_pre(const void* lab) {
    int i = blockIdx.x * blockDim.x + threadIdx.x;
    if (i < NC) g_cnt[i] = 0;
    if (i == 0) {
        const int* w = (const int*)lab;
        int bad = 0;
        #pragma unroll
        for (int k = 1; k < 128; k += 2) bad |= w[k];
        g_is64 = (bad == 0);
    }
}

// ---------------- kernel 1: normalize + fp16 + class lists -----------------
__global__ void k_norm(const float* __restrict__ in, const void* __restrict__ lab) {
    int gid = blockIdx.x * blockDim.x + threadIdx.x;
    if (gid < N) g_sall[gid] = 0.0f;
    int row  = blockIdx.x * 8 + (threadIdx.x >> 5);
    int lane = threadIdx.x & 31;
    float4 v = *(const float4*)(in + row * D + lane * 4);
    float ss = v.x * v.x + v.y * v.y + v.z * v.z + v.w * v.w;
    #pragma unroll
    for (int m = 16; m >= 1; m >>= 1) ss += __shfl_xor_sync(0xffffffffu, ss, m);
    float inv = 1.0f / fmaxf(sqrtf(ss), 1e-12f);
    float o[4] = {v.x * inv, v.y * inv, v.z * inv, v.w * inv};
    float4 of; of.x = o[0]; of.y = o[1]; of.z = o[2]; of.w = o[3];
    *(float4*)(g_enorm + row * D + lane * 4) = of;
    __half2 h0 = __floats2half2_rn(o[0], o[1]);
    __half2 h1 = __floats2half2_rn(o[2], o[3]);
    *(__half2*)(g_h16 + row * D + lane * 4)     = h0;
    *(__half2*)(g_h16 + row * D + lane * 4 + 2) = h1;
    if (lane == 0) {
        int c = get_label(lab, row);
        int p = atomicAdd(&g_cnt[c], 1);
        if (p < MAXM) g_members[c * MAXM + p] = row;
    }
}

// ---------------- kernel 2: per-class positives, warp-per-anchor (exact) ---
__global__ void k_class() {
    int c = blockIdx.x;
    __shared__ int   mlist[MAXM];
    __shared__ float se[MAXM * 129];
    int m = g_cnt[c];
    if (m > MAXM) m = MAXM;
    if (m == 0) return;
    int tid = threadIdx.x, lane = tid & 31, wid = tid >> 5;
    if (tid < m) mlist[tid] = g_members[c * MAXM + tid];
    __syncthreads();
    for (int p = tid; p < m * D; p += blockDim.x) {
        int r = p >> 7, k = p & 127;
        se[r * 129 + k] = g_enorm[mlist[r] * D + k];
    }
    __syncthreads();
    for (int a = wid; a < m; a += 4) {
        int b0 = lane, b1 = lane + 32;
        float s0 = 0.0f, s1 = 0.0f;
        const float* ra = se + a * 129;
        #pragma unroll 8
        for (int k = 0; k < D; k++) {
            float av = ra[k];
            s0 = fmaf(av, se[b0 * 129 + k], s0);
            s1 = fmaf(av, se[b1 * 129 + k], s1);
        }
        float ap0 = -1e30f, ap1 = -1e30f, an0 = 0.0f, an1 = 0.0f;
        bool v0 = (b0 < m && b0 != a), v1 = (b1 < m && b1 != a);
        if (v0) { ap0 = -80.0f * fmaxf(1.4f - s0, 0.0f) * (s0 - 0.6f); an0 = an_exp(s0); }
        if (v1) { ap1 = -80.0f * fmaxf(1.4f - s1, 0.0f) * (s1 - 0.6f); an1 = an_exp(s1); }
        float mx = fmaxf(ap0, ap1);
        #pragma unroll
        for (int k = 16; k >= 1; k >>= 1) mx = fmaxf(mx, __shfl_xor_sync(0xffffffffu, mx, k));
        float es = (v0 ? __expf(ap0 - mx) : 0.0f) + (v1 ? __expf(ap1 - mx) : 0.0f);
        float sa = an0 + an1;
        #pragma unroll
        for (int k = 16; k >= 1; k >>= 1) {
            es += __shfl_xor_sync(0xffffffffu, es, k);
            sa += __shfl_xor_sync(0xffffffffu, sa, k);
        }
        if (lane == 0) {
            g_lsep[mlist[a]]    = mx + logf(es);
            g_samesum[mlist[a]] = sa;
        }
    }
}

// -------- kernel 3: single-product fp16 mma.sync GEMM + fused an-sumexp ----
// Proven R6/R9 structure, 2 smem arrays: A_h (rows), B_h (cols). sim = h.h'
#define SROW   144
#define SA_H   0
#define SB_H   (128 * SROW)
#define SMEM_SZ (2 * 128 * SROW)   // 36864 B

__global__ void __launch_bounds__(256, 2) k_main_m() {
    int b = blockIdx.x;
    int r = (int)((__fsqrt_rn(8.0f * (float)b + 1.0f) - 1.0f) * 0.5f);
    while ((r + 1) * (r + 2) / 2 <= b) r++;
    while (r * (r + 1) / 2 > b) r--;
    int bi = b - r * (r + 1) / 2;
    int bj = r;

    extern __shared__ char sm[];
    uint32_t sb = smem_u32(sm);
    int tid = threadIdx.x;
    int lane = tid & 31, wid = tid >> 5;
    int g = lane >> 2, t = lane & 3;
    int wm = wid & 3, wn = wid >> 2;
    int rowBase = bi * 128, colBase = bj * 128;

    uint32_t lmo = (uint32_t)((lane & 15) * SROW + (lane >> 4) * 16);
    uint32_t aBaseH = sb + SA_H + (uint32_t)(wm * 32) * SROW + lmo;
    uint32_t bBaseH = sb + SB_H + (uint32_t)(wn * 64) * SROW + lmo;

    float acc[2][8][4];
    #pragma unroll
    for (int i = 0; i < 2; i++)
        #pragma unroll
        for (int j = 0; j < 8; j++)
            #pragma unroll
            for (int e = 0; e < 4; e++) acc[i][j][e] = 0.0f;

    for (int kc = 0; kc < 2; kc++) {
        #pragma unroll
        for (int it = 0; it < 4; it++) {
            int idx = it * 256 + tid;
            int row = idx >> 3, k8 = idx & 7;
            uint32_t so = (uint32_t)(row * SROW + k8 * 16);
            size_t gA = (size_t)(rowBase + row) * 16 + kc * 8 + k8;
            size_t gB = (size_t)(colBase + row) * 16 + kc * 8 + k8;
            cpa16(sb + SA_H + so, (const uint4*)g_h16 + gA);
            cpa16(sb + SB_H + so, (const uint4*)g_h16 + gB);
        }
        asm volatile("cp.async.commit_group;" ::: "memory");
        asm volatile("cp.async.wait_group 0;" ::: "memory");
        __syncthreads();

        #pragma unroll
        for (int ks = 0; ks < 4; ks++) {
            uint32_t ko = (uint32_t)(ks * 32);
            uint32_t ah[2][4];
            ldsm4(ah[0], aBaseH + ko);
            ldsm4(ah[1], aBaseH + ko + 16 * SROW);
            #pragma unroll
            for (int jp = 0; jp < 4; jp++) {
                uint32_t bh[4];
                ldsm4(bh, bBaseH + ko + (uint32_t)(jp * 16) * SROW);
                mma_f16(acc[0][2 * jp],     ah[0], bh[0], bh[2]);
                mma_f16(acc[1][2 * jp],     ah[1], bh[0], bh[2]);
                mma_f16(acc[0][2 * jp + 1], ah[0], bh[1], bh[3]);
                mma_f16(acc[1][2 * jp + 1], ah[1], bh[1], bh[3]);
            }
        }
        __syncthreads();
    }

    bool diag = (bi == bj);
    #pragma unroll
    for (int i = 0; i < 2; i++)
        #pragma unroll
        for (int j = 0; j < 8; j++)
            #pragma unroll
            for (int e = 0; e < 4; e++) {
                float x = an_exp(acc[i][j][e]);
                if (diag) {
                    int rl = wm * 32 + i * 16 + g + ((e >> 1) << 3);
                    int cl = wn * 64 + j * 8 + 2 * t + (e & 1);
                    if (rl == cl) x = 0.0f;
                }
                acc[i][j][e] = x;
            }
    // row sums
    #pragma unroll
    for (int i = 0; i < 2; i++)
        #pragma unroll
        for (int h = 0; h < 2; h++) {
            float v = 0.0f;
            #pragma unroll
            for (int j = 0; j < 8; j++) v += acc[i][j][2 * h] + acc[i][j][2 * h + 1];
            v += __shfl_xor_sync(0xffffffffu, v, 1);
            v += __shfl_xor_sync(0xffffffffu, v, 2);
            if (t == 0)
                atomicAdd(&g_sall[rowBase + wm * 32 + i * 16 + g + h * 8], v);
        }
    // col sums (only off-diagonal tiles)
    if (!diag) {
        #pragma unroll
        for (int j = 0; j < 8; j++)
            #pragma unroll
            for (int bb = 0; bb < 2; bb++) {
                float v = acc[0][j][bb] + acc[0][j][2 + bb] +
                          acc[1][j][bb] + acc[1][j][2 + bb];
                v += __shfl_xor_sync(0xffffffffu, v, 4);
                v += __shfl_xor_sync(0xffffffffu, v, 8);
                v += __shfl_xor_sync(0xffffffffu, v, 16);
                if (g == 0)
                    atomicAdd(&g_sall[colBase + wn * 64 + j * 8 + 2 * t + bb], v);
            }
    }
}

// ---------------- kernel 4a: parallel finalize (one anchor per thread) -----
__global__ void k_finalp(const void* __restrict__ lab) {
    __shared__ float ssum[256];
    __shared__ int   scnt[256];
    int tid = threadIdx.x;
    int i = blockIdx.x * 256 + tid;
    int c = get_label(lab, i);
    int m = g_cnt[c];
    int np = m - 1, nn = N - m;
    float sp = 0.0f;
    int ok = 0;
    if (np > 0 && nn > 0) {
        float sneg = g_sall[i] - g_samesum[i];
        sneg = fmaxf(sneg, 1e-30f);
        float x = g_lsep[i] + logf((float)nn) + logf(sneg) + logf((float)np);
        sp = (x > 0.0f) ? (x + log1pf(__expf(-x))) : log1pf(__expf(x));
        ok = 1;
    }
    ssum[tid] = sp; scnt[tid] = ok;
    __syncthreads();
    #pragma unroll
    for (int s = 128; s > 0; s >>= 1) {
        if (tid < s) { ssum[tid] += ssum[tid + s]; scnt[tid] += scnt[tid + s]; }
        __syncthreads();
    }
    if (tid == 0) { g_part[blockIdx.x] = ssum[0]; g_pcnt[blockIdx.x] = scnt[0]; }
}

// ---------------- kernel 4b: deterministic 32-way reduce -------------------
__global__ void k_final2(float* __restrict__ out) {
    int lane = threadIdx.x;
    float v = g_part[lane];
    int   c = g_pcnt[lane];
    #pragma unroll
    for (int k = 16; k >= 1; k >>= 1) {
        v += __shfl_xor_sync(0xffffffffu, v, k);
        c += __shfl_xor_sync(0xffffffffu, c, k);
    }
    if (lane == 0) out[0] = v / fmaxf((float)c, 1.0f);
}

// ---------------- launch ---------------------------------------------------
extern "C" void kernel_launch(void* const* d_in, const int* in_sizes, int n_in,
                              void* d_out, int out_size) {
    const float* embeds = (const float*)d_in[0];
    const void*  labels = d_in[1];
    float* out = (float*)d_out;
    (void)in_sizes; (void)n_in; (void)out_size;

    cudaFuncSetAttribute(k_main_m, cudaFuncAttributeMaxDynamicSharedMemorySize, SMEM_SZ);

    k_pre<<<2, 256>>>(labels);
    k_norm<<<N / 8, 256>>>(embeds, labels);
    k_class<<<NC, 128>>>();
    k_main_m<<<2080, 256, SMEM_SZ>>>();
    k_finalp<<<32, 256>>>(labels);
    k_final2<<<1, 32>>>(out);
}

// round 11
// speedup vs baseline: 5.9096x; 1.0476x over previous
#include <cuda_runtime.h>
#include <cuda_fp16.h>
#include <math.h>
#include <stdint.h>

#define N 8192
#define D 128
#define NC 512
#define MAXM 64

// ---------------- scratch (device globals; no allocation allowed) ----------
__device__ __align__(16) float g_enorm[N * D];
__device__ __align__(16) __half g_h16[N * D];   // fp16(x)
__device__ int   g_cnt[NC];
__device__ int   g_members[NC * MAXM];
__device__ float g_lsep[N];
__device__ float g_samesum[N];
__device__ float g_sall[N];
__device__ float g_part[32];
__device__ int   g_pcnt[32];
__device__ int   g_is64;

__device__ __forceinline__ float an_exp(float s) {
    float t = fmaxf(s + 0.4f, 0.0f);
    return __expf(80.0f * t * (s - 0.4f));
}

__device__ __forceinline__ int get_label(const void* lab, int i) {
    if (g_is64) return (int)((const long long*)lab)[i];
    return ((const int*)lab)[i];
}

__device__ __forceinline__ uint32_t smem_u32(const void* p) {
    uint32_t a;
    asm("{ .reg .u64 t; cvta.to.shared.u64 t, %1; cvt.u32.u64 %0, t; }" : "=r"(a) : "l"(p));
    return a;
}
__device__ __forceinline__ void cpa16(uint32_t dst, const void* src) {
    asm volatile("cp.async.cg.shared.global [%0], [%1], 16;" :: "r"(dst), "l"(src) : "memory");
}
__device__ __forceinline__ void ldsm4(uint32_t* r, uint32_t addr) {
    asm volatile("ldmatrix.sync.aligned.m8n8.x4.shared.b16 {%0,%1,%2,%3}, [%4];"
        : "=r"(r[0]), "=r"(r[1]), "=r"(r[2]), "=r"(r[3]) : "r"(addr));
}
__device__ __forceinline__ void mma_f16(float* d, const uint32_t* a, uint32_t b0, uint32_t b1) {
    asm volatile(
        "mma.sync.aligned.m16n8k16.row.col.f32.f16.f16.f32 "
        "{%0,%1,%2,%3}, {%4,%5,%6,%7}, {%8,%9}, {%0,%1,%2,%3};\n"
        : "+f"(d[0]), "+f"(d[1]), "+f"(d[2]), "+f"(d[3])
        : "r"(a[0]), "r"(a[1]), "r"(a[2]), "r"(a[3]), "r"(b0), "r"(b1));
}

// ---------------- kernel 0: tiny pre (g_cnt zero + dtype flag) -------------
__global__ void k_pre(const void* lab) {
    int i = blockIdx.x * blockDim.x + threadIdx.x;
    if (i < NC) g_cnt[i] = 0;
    if (i == 0) {
        const int* w = (const int*)lab;
        int bad = 0;
        #pragma unroll
        for (int k = 1; k < 128; k += 2) bad |= w[k];
        g_is64 = (bad == 0);
    }
}

// ---------------- kernel 1: normalize + fp16 + class lists -----------------
__global__ void k_norm(const float* __restrict__ in, const void* __restrict__ lab) {
    int gid = blockIdx.x * blockDim.x + threadIdx.x;
    if (gid < N) g_sall[gid] = 0.0f;
    int row  = blockIdx.x * 8 + (threadIdx.x >> 5);
    int lane = threadIdx.x & 31;
    float4 v = *(const float4*)(in + row * D + lane * 4);
    float ss = v.x * v.x + v.y * v.y + v.z * v.z + v.w * v.w;
    #pragma unroll
    for (int m = 16; m >= 1; m >>= 1) ss += __shfl_xor_sync(0xffffffffu, ss, m);
    float inv = 1.0f / fmaxf(sqrtf(ss), 1e-12f);
    float o[4] = {v.x * inv, v.y * inv, v.z * inv, v.w * inv};
    float4 of; of.x = o[0]; of.y = o[1]; of.z = o[2]; of.w = o[3];
    *(float4*)(g_enorm + row * D + lane * 4) = of;
    __half2 h0 = __floats2half2_rn(o[0], o[1]);
    __half2 h1 = __floats2half2_rn(o[2], o[3]);
    *(__half2*)(g_h16 + row * D + lane * 4)     = h0;
    *(__half2*)(g_h16 + row * D + lane * 4 + 2) = h1;
    if (lane == 0) {
        int c = get_label(lab, row);
        int p = atomicAdd(&g_cnt[c], 1);
        if (p < MAXM) g_members[c * MAXM + p] = row;
    }
}

// ---------------- kernel 2: per-class positives, warp-per-anchor (exact) ---
__global__ void k_class() {
    int c = blockIdx.x;
    __shared__ int   mlist[MAXM];
    __shared__ float se[MAXM * 129];
    int m = g_cnt[c];
    if (m > MAXM) m = MAXM;
    if (m == 0) return;
    int tid = threadIdx.x, lane = tid & 31, wid = tid >> 5;
    if (tid < m) mlist[tid] = g_members[c * MAXM + tid];
    __syncthreads();
    for (int p = tid; p < m * D; p += blockDim.x) {
        int r = p >> 7, k = p & 127;
        se[r * 129 + k] = g_enorm[mlist[r] * D + k];
    }
    __syncthreads();
    for (int a = wid; a < m; a += 4) {
        int b0 = lane, b1 = lane + 32;
        float s0 = 0.0f, s1 = 0.0f;
        const float* ra = se + a * 129;
        #pragma unroll 8
        for (int k = 0; k < D; k++) {
            float av = ra[k];
            s0 = fmaf(av, se[b0 * 129 + k], s0);
            s1 = fmaf(av, se[b1 * 129 + k], s1);
        }
        float ap0 = -1e30f, ap1 = -1e30f, an0 = 0.0f, an1 = 0.0f;
        bool v0 = (b0 < m && b0 != a), v1 = (b1 < m && b1 != a);
        if (v0) { ap0 = -80.0f * fmaxf(1.4f - s0, 0.0f) * (s0 - 0.6f); an0 = an_exp(s0); }
        if (v1) { ap1 = -80.0f * fmaxf(1.4f - s1, 0.0f) * (s1 - 0.6f); an1 = an_exp(s1); }
        float mx = fmaxf(ap0, ap1);
        #pragma unroll
        for (int k = 16; k >= 1; k >>= 1) mx = fmaxf(mx, __shfl_xor_sync(0xffffffffu, mx, k));
        float es = (v0 ? __expf(ap0 - mx) : 0.0f) + (v1 ? __expf(ap1 - mx) : 0.0f);
        float sa = an0 + an1;
        #pragma unroll
        for (int k = 16; k >= 1; k >>= 1) {
            es += __shfl_xor_sync(0xffffffffu, es, k);
            sa += __shfl_xor_sync(0xffffffffu, sa, k);
        }
        if (lane == 0) {
            g_lsep[mlist[a]]    = mx + logf(es);
            g_samesum[mlist[a]] = sa;
        }
    }
}

// ---- kernel 3: fp16 mma.sync GEMM, double-buffered prefetch + an-sumexp ---
// Two phase-buffers; both phases' loads issued up front as separate commit
// groups; compute(phase0) overlaps load(phase1). No buffer reuse -> the
// end-of-phase __syncthreads is gone.
#define SROW   144
#define ARR    (128 * SROW)       // 18432 B per array
#define STG    (2 * ARR)          // 36864 B per phase (A + B)
#define SMEM_SZ (2 * STG)         // 73728 B

__global__ void __launch_bounds__(256, 2) k_main_m() {
    int b = blockIdx.x;
    int r = (int)((__fsqrt_rn(8.0f * (float)b + 1.0f) - 1.0f) * 0.5f);
    while ((r + 1) * (r + 2) / 2 <= b) r++;
    while (r * (r + 1) / 2 > b) r--;
    int bi = b - r * (r + 1) / 2;
    int bj = r;

    extern __shared__ char sm[];
    uint32_t sb = smem_u32(sm);
    int tid = threadIdx.x;
    int lane = tid & 31, wid = tid >> 5;
    int g = lane >> 2, t = lane & 3;
    int wm = wid & 3, wn = wid >> 2;
    int rowBase = bi * 128, colBase = bj * 128;

    uint32_t lmo = (uint32_t)((lane & 15) * SROW + (lane >> 4) * 16);
    uint32_t aOff = (uint32_t)(wm * 32) * SROW + lmo;          // + phase*STG
    uint32_t bOff = (uint32_t)ARR + (uint32_t)(wn * 64) * SROW + lmo;

    float acc[2][8][4];
    #pragma unroll
    for (int i = 0; i < 2; i++)
        #pragma unroll
        for (int j = 0; j < 8; j++)
            #pragma unroll
            for (int e = 0; e < 4; e++) acc[i][j][e] = 0.0f;

    // ---- prologue: issue BOTH phases' loads (two commit groups) ----
    #pragma unroll
    for (int kc = 0; kc < 2; kc++) {
        uint32_t pb = sb + (uint32_t)kc * STG;
        #pragma unroll
        for (int it = 0; it < 4; it++) {
            int idx = it * 256 + tid;
            int row = idx >> 3, k8 = idx & 7;
            uint32_t so = (uint32_t)(row * SROW + k8 * 16);
            size_t gA = (size_t)(rowBase + row) * 16 + kc * 8 + k8;
            size_t gB = (size_t)(colBase + row) * 16 + kc * 8 + k8;
            cpa16(pb + so,       (const uint4*)g_h16 + gA);
            cpa16(pb + ARR + so, (const uint4*)g_h16 + gB);
        }
        asm volatile("cp.async.commit_group;" ::: "memory");
    }

    #pragma unroll
    for (int kc = 0; kc < 2; kc++) {
        if (kc == 0) asm volatile("cp.async.wait_group 1;" ::: "memory");
        else         asm volatile("cp.async.wait_group 0;" ::: "memory");
        __syncthreads();
        uint32_t pb = sb + (uint32_t)kc * STG;
        #pragma unroll
        for (int ks = 0; ks < 4; ks++) {
            uint32_t ko = (uint32_t)(ks * 32);
            uint32_t ah[2][4];
            ldsm4(ah[0], pb + aOff + ko);
            ldsm4(ah[1], pb + aOff + ko + 16 * SROW);
            #pragma unroll
            for (int jp = 0; jp < 4; jp++) {
                uint32_t bh[4];
                ldsm4(bh, pb + bOff + ko + (uint32_t)(jp * 16) * SROW);
                mma_f16(acc[0][2 * jp],     ah[0], bh[0], bh[2]);
                mma_f16(acc[1][2 * jp],     ah[1], bh[0], bh[2]);
                mma_f16(acc[0][2 * jp + 1], ah[0], bh[1], bh[3]);
                mma_f16(acc[1][2 * jp + 1], ah[1], bh[1], bh[3]);
            }
        }
    }

    bool diag = (bi == bj);
    #pragma unroll
    for (int i = 0; i < 2; i++)
        #pragma unroll
        for (int j = 0; j < 8; j++)
            #pragma unroll
            for (int e = 0; e < 4; e++) {
                float x = an_exp(acc[i][j][e]);
                if (diag) {
                    int rl = wm * 32 + i * 16 + g + ((e >> 1) << 3);
                    int cl = wn * 64 + j * 8 + 2 * t + (e & 1);
                    if (rl == cl) x = 0.0f;
                }
                acc[i][j][e] = x;
            }
    // row sums
    #pragma unroll
    for (int i = 0; i < 2; i++)
        #pragma unroll
        for (int h = 0; h < 2; h++) {
            float v = 0.0f;
            #pragma unroll
            for (int j = 0; j < 8; j++) v += acc[i][j][2 * h] + acc[i][j][2 * h + 1];
            v += __shfl_xor_sync(0xffffffffu, v, 1);
            v += __shfl_xor_sync(0xffffffffu, v, 2);
            if (t == 0)
                atomicAdd(&g_sall[rowBase + wm * 32 + i * 16 + g + h * 8], v);
        }
    // col sums (only off-diagonal tiles)
    if (!diag) {
        #pragma unroll
        for (int j = 0; j < 8; j++)
            #pragma unroll
            for (int bb = 0; bb < 2; bb++) {
                float v = acc[0][j][bb] + acc[0][j][2 + bb] +
                          acc[1][j][bb] + acc[1][j][2 + bb];
                v += __shfl_xor_sync(0xffffffffu, v, 4);
                v += __shfl_xor_sync(0xffffffffu, v, 8);
                v += __shfl_xor_sync(0xffffffffu, v, 16);
                if (g == 0)
                    atomicAdd(&g_sall[colBase + wn * 64 + j * 8 + 2 * t + bb], v);
            }
    }
}

// ---------------- kernel 4a: parallel finalize (one anchor per thread) -----
__global__ void k_finalp(const void* __restrict__ lab) {
    __shared__ float ssum[256];
    __shared__ int   scnt[256];
    int tid = threadIdx.x;
    int i = blockIdx.x * 256 + tid;
    int c = get_label(lab, i);
    int m = g_cnt[c];
    int np = m - 1, nn = N - m;
    float sp = 0.0f;
    int ok = 0;
    if (np > 0 && nn > 0) {
        float sneg = g_sall[i] - g_samesum[i];
        sneg = fmaxf(sneg, 1e-30f);
        float x = g_lsep[i] + logf((float)nn) + logf(sneg) + logf((float)np);
        sp = (x > 0.0f) ? (x + log1pf(__expf(-x))) : log1pf(__expf(x));
        ok = 1;
    }
    ssum[tid] = sp; scnt[tid] = ok;
    __syncthreads();
    #pragma unroll
    for (int s = 128; s > 0; s >>= 1) {
        if (tid < s) { ssum[tid] += ssum[tid + s]; scnt[tid] += scnt[tid + s]; }
        __syncthreads();
    }
    if (tid == 0) { g_part[blockIdx.x] = ssum[0]; g_pcnt[blockIdx.x] = scnt[0]; }
}

// ---------------- kernel 4b: deterministic 32-way reduce -------------------
__global__ void k_final2(float* __restrict__ out) {
    int lane = threadIdx.x;
    float v = g_part[lane];
    int   c = g_pcnt[lane];
    #pragma unroll
    for (int k = 16; k >= 1; k >>= 1) {
        v += __shfl_xor_sync(0xffffffffu, v, k);
        c += __shfl_xor_sync(0xffffffffu, c, k);
    }
    if (lane == 0) out[0] = v / fmaxf((float)c, 1.0f);
}

// ---------------- launch ---------------------------------------------------
extern "C" void kernel_launch(void* const* d_in, const int* in_sizes, int n_in,
                              void* d_out, int out_size) {
    const float* embeds = (const float*)d_in[0];
    const void*  labels = d_in[1];
    float* out = (float*)d_out;
    (void)in_sizes; (void)n_in; (void)out_size;

    cudaFuncSetAttribute(k_main_m, cudaFuncAttributeMaxDynamicSharedMemorySize, SMEM_SZ);

    k_pre<<<2, 256>>>(labels);
    k_norm<<<N / 8, 256>>>(embeds, labels);
    k_class<<<NC, 128>>>();
    k_main_m<<<2080, 256, SMEM_SZ>>>();
    k_finalp<<<32, 256>>>(labels);
    k_final2<<<1, 32>>>(out);
}

// round 12
// speedup vs baseline: 6.7202x; 1.1372x over previous
#include <cuda_runtime.h>
#include <cuda_fp16.h>
#include <math.h>
#include <stdint.h>

#define N 8192
#define D 128
#define NC 512
#define MAXM 64

// ---------------- scratch (device globals; no allocation allowed) ----------
__device__ __align__(16) float g_enorm[N * D];
__device__ __align__(16) __half g_h16[N * D];   // fp16(x)
__device__ int   g_cnt[NC];          // zeroed at module load; re-zeroed each run by k_final_f
__device__ int   g_members[NC * MAXM];
__device__ float g_lsep[N];
__device__ float g_samesum[N];
__device__ float g_sall[N];
__device__ float g_part[32];
__device__ int   g_pcnt[32];
__device__ unsigned g_done;          // zeroed at load; reset each run by k_final_f

// an_exp via ex2.approx with folded log2e: exp(80*t*(s-.4)) = 2^(115.4156*t*(s-.4))
__device__ __forceinline__ float an_exp(float s) {
    float t = fmaxf(s + 0.4f, 0.0f);
    float x = 115.41560327111707f * t * (s - 0.4f);
    float r;
    asm("ex2.approx.f32 %0, %1;" : "=f"(r) : "f"(x));
    return r;
}

__device__ __forceinline__ uint32_t smem_u32(const void* p) {
    uint32_t a;
    asm("{ .reg .u64 t; cvta.to.shared.u64 t, %1; cvt.u32.u64 %0, t; }" : "=r"(a) : "l"(p));
    return a;
}
__device__ __forceinline__ void cpa16(uint32_t dst, const void* src) {
    asm volatile("cp.async.cg.shared.global [%0], [%1], 16;" :: "r"(dst), "l"(src) : "memory");
}
__device__ __forceinline__ void ldsm4(uint32_t* r, uint32_t addr) {
    asm volatile("ldmatrix.sync.aligned.m8n8.x4.shared.b16 {%0,%1,%2,%3}, [%4];"
        : "=r"(r[0]), "=r"(r[1]), "=r"(r[2]), "=r"(r[3]) : "r"(addr));
}
__device__ __forceinline__ void mma_f16(float* d, const uint32_t* a, uint32_t b0, uint32_t b1) {
    asm volatile(
        "mma.sync.aligned.m16n8k16.row.col.f32.f16.f16.f32 "
        "{%0,%1,%2,%3}, {%4,%5,%6,%7}, {%8,%9}, {%0,%1,%2,%3};\n"
        : "+f"(d[0]), "+f"(d[1]), "+f"(d[2]), "+f"(d[3])
        : "r"(a[0]), "r"(a[1]), "r"(a[2]), "r"(a[3]), "r"(b0), "r"(b1));
}

// per-block label dtype detect: int64 labels have all odd 32-bit words == 0
__device__ __forceinline__ int detect_is64(const void* lab, int tid) {
    int w = (tid < 64) ? ((const int*)lab)[2 * tid + 1] : 0;
    return !__syncthreads_or(w != 0);
}

// ---------------- kernel 1: normalize + fp16 + class lists -----------------
__global__ void k_norm(const float* __restrict__ in, const void* __restrict__ lab) {
    int tid = threadIdx.x;
    int is64 = detect_is64(lab, tid);
    int gid = blockIdx.x * blockDim.x + tid;
    if (gid < N) g_sall[gid] = 0.0f;
    int row  = blockIdx.x * 8 + (tid >> 5);
    int lane = tid & 31;
    float4 v = *(const float4*)(in + row * D + lane * 4);
    float ss = v.x * v.x + v.y * v.y + v.z * v.z + v.w * v.w;
    #pragma unroll
    for (int m = 16; m >= 1; m >>= 1) ss += __shfl_xor_sync(0xffffffffu, ss, m);
    float inv = 1.0f / fmaxf(sqrtf(ss), 1e-12f);
    float o[4] = {v.x * inv, v.y * inv, v.z * inv, v.w * inv};
    float4 of; of.x = o[0]; of.y = o[1]; of.z = o[2]; of.w = o[3];
    *(float4*)(g_enorm + row * D + lane * 4) = of;
    __half2 h0 = __floats2half2_rn(o[0], o[1]);
    __half2 h1 = __floats2half2_rn(o[2], o[3]);
    *(__half2*)(g_h16 + row * D + lane * 4)     = h0;
    *(__half2*)(g_h16 + row * D + lane * 4 + 2) = h1;
    if (lane == 0) {
        int c = is64 ? (int)((const long long*)lab)[row] : ((const int*)lab)[row];
        int p = atomicAdd(&g_cnt[c], 1);
        if (p < MAXM) g_members[c * MAXM + p] = row;
    }
}

// ---------------- class block body (runs inside k_main_f) ------------------
__device__ void class_block(int c, char* smraw) {
    int*   mlist = (int*)smraw;                 // 64 ints
    float* se    = (float*)(smraw + 256);       // 64*129 floats = 33024 B
    int m = g_cnt[c];
    if (m > MAXM) m = MAXM;
    if (m == 0) return;
    int tid = threadIdx.x, lane = tid & 31, wid = tid >> 5;
    if (tid < m) mlist[tid] = g_members[c * MAXM + tid];
    __syncthreads();
    for (int p = tid; p < m * D; p += 256) {
        int r = p >> 7, k = p & 127;
        se[r * 129 + k] = g_enorm[mlist[r] * D + k];
    }
    __syncthreads();
    for (int a = wid; a < m; a += 8) {
        int b0 = lane, b1 = lane + 32;
        float s0 = 0.0f, s1 = 0.0f;
        const float* ra = se + a * 129;
        #pragma unroll 8
        for (int k = 0; k < D; k++) {
            float av = ra[k];
            s0 = fmaf(av, se[b0 * 129 + k], s0);
            s1 = fmaf(av, se[b1 * 129 + k], s1);
        }
        float ap0 = -1e30f, ap1 = -1e30f, an0 = 0.0f, an1 = 0.0f;
        bool v0 = (b0 < m && b0 != a), v1 = (b1 < m && b1 != a);
        if (v0) { ap0 = -80.0f * fmaxf(1.4f - s0, 0.0f) * (s0 - 0.6f); an0 = an_exp(s0); }
        if (v1) { ap1 = -80.0f * fmaxf(1.4f - s1, 0.0f) * (s1 - 0.6f); an1 = an_exp(s1); }
        float mx = fmaxf(ap0, ap1);
        #pragma unroll
        for (int k = 16; k >= 1; k >>= 1) mx = fmaxf(mx, __shfl_xor_sync(0xffffffffu, mx, k));
        float es = (v0 ? __expf(ap0 - mx) : 0.0f) + (v1 ? __expf(ap1 - mx) : 0.0f);
        float sa = an0 + an1;
        #pragma unroll
        for (int k = 16; k >= 1; k >>= 1) {
            es += __shfl_xor_sync(0xffffffffu, es, k);
            sa += __shfl_xor_sync(0xffffffffu, sa, k);
        }
        if (lane == 0) {
            g_lsep[mlist[a]]    = mx + logf(es);
            g_samesum[mlist[a]] = sa;
        }
    }
}

// ---- kernel 3 (fused): GEMM tiles + class blocks, interleaved 1-in-5 ------
#define SROW   144
#define ARR    (128 * SROW)       // 18432 B per array
#define STG    (2 * ARR)          // 36864 B per phase (A + B)
#define SMEM_SZ (2 * STG)         // 73728 B
#define NBLK   (2080 + NC)        // 2592

__global__ void __launch_bounds__(256, 2) k_main_f() {
    extern __shared__ char sm[];
    int blk = blockIdx.x;
    // interleave: blocks b<2560 with b%5==4 are class blocks (512 total)
    int b;
    if (blk < 2560) {
        if (blk % 5 == 4) { class_block(blk / 5, sm); return; }
        b = blk - blk / 5;
    } else {
        b = blk - NC;
    }

    int r = (int)((__fsqrt_rn(8.0f * (float)b + 1.0f) - 1.0f) * 0.5f);
    while ((r + 1) * (r + 2) / 2 <= b) r++;
    while (r * (r + 1) / 2 > b) r--;
    int bi = b - r * (r + 1) / 2;
    int bj = r;

    uint32_t sb = smem_u32(sm);
    int tid = threadIdx.x;
    int lane = tid & 31, wid = tid >> 5;
    int g = lane >> 2, t = lane & 3;
    int wm = wid & 3, wn = wid >> 2;
    int rowBase = bi * 128, colBase = bj * 128;

    uint32_t lmo = (uint32_t)((lane & 15) * SROW + (lane >> 4) * 16);
    uint32_t aOff = (uint32_t)(wm * 32) * SROW + lmo;
    uint32_t bOff = (uint32_t)ARR + (uint32_t)(wn * 64) * SROW + lmo;

    float acc[2][8][4];
    #pragma unroll
    for (int i = 0; i < 2; i++)
        #pragma unroll
        for (int j = 0; j < 8; j++)
            #pragma unroll
            for (int e = 0; e < 4; e++) acc[i][j][e] = 0.0f;

    // prologue: both phases' loads up front (two commit groups)
    #pragma unroll
    for (int kc = 0; kc < 2; kc++) {
        uint32_t pb = sb + (uint32_t)kc * STG;
        #pragma unroll
        for (int it = 0; it < 4; it++) {
            int idx = it * 256 + tid;
            int row = idx >> 3, k8 = idx & 7;
            uint32_t so = (uint32_t)(row * SROW + k8 * 16);
            size_t gA = (size_t)(rowBase + row) * 16 + kc * 8 + k8;
            size_t gB = (size_t)(colBase + row) * 16 + kc * 8 + k8;
            cpa16(pb + so,       (const uint4*)g_h16 + gA);
            cpa16(pb + ARR + so, (const uint4*)g_h16 + gB);
        }
        asm volatile("cp.async.commit_group;" ::: "memory");
    }

    #pragma unroll
    for (int kc = 0; kc < 2; kc++) {
        if (kc == 0) asm volatile("cp.async.wait_group 1;" ::: "memory");
        else         asm volatile("cp.async.wait_group 0;" ::: "memory");
        __syncthreads();
        uint32_t pb = sb + (uint32_t)kc * STG;
        #pragma unroll
        for (int ks = 0; ks < 4; ks++) {
            uint32_t ko = (uint32_t)(ks * 32);
            uint32_t ah[2][4];
            ldsm4(ah[0], pb + aOff + ko);
            ldsm4(ah[1], pb + aOff + ko + 16 * SROW);
            #pragma unroll
            for (int jp = 0; jp < 4; jp++) {
                uint32_t bh[4];
                ldsm4(bh, pb + bOff + ko + (uint32_t)(jp * 16) * SROW);
                mma_f16(acc[0][2 * jp],     ah[0], bh[0], bh[2]);
                mma_f16(acc[1][2 * jp],     ah[1], bh[0], bh[2]);
                mma_f16(acc[0][2 * jp + 1], ah[0], bh[1], bh[3]);
                mma_f16(acc[1][2 * jp + 1], ah[1], bh[1], bh[3]);
            }
        }
    }

    bool diag = (bi == bj);
    #pragma unroll
    for (int i = 0; i < 2; i++)
        #pragma unroll
        for (int j = 0; j < 8; j++)
            #pragma unroll
            for (int e = 0; e < 4; e++) {
                float x = an_exp(acc[i][j][e]);
                if (diag) {
                    int rl = wm * 32 + i * 16 + g + ((e >> 1) << 3);
                    int cl = wn * 64 + j * 8 + 2 * t + (e & 1);
                    if (rl == cl) x = 0.0f;
                }
                acc[i][j][e] = x;
            }
    // row sums
    #pragma unroll
    for (int i = 0; i < 2; i++)
        #pragma unroll
        for (int h = 0; h < 2; h++) {
            float v = 0.0f;
            #pragma unroll
            for (int j = 0; j < 8; j++) v += acc[i][j][2 * h] + acc[i][j][2 * h + 1];
            v += __shfl_xor_sync(0xffffffffu, v, 1);
            v += __shfl_xor_sync(0xffffffffu, v, 2);
            if (t == 0)
                atomicAdd(&g_sall[rowBase + wm * 32 + i * 16 + g + h * 8], v);
        }
    // col sums (only off-diagonal tiles)
    if (!diag) {
        #pragma unroll
        for (int j = 0; j < 8; j++)
            #pragma unroll
            for (int bb = 0; bb < 2; bb++) {
                float v = acc[0][j][bb] + acc[0][j][2 + bb] +
                          acc[1][j][bb] + acc[1][j][2 + bb];
                v += __shfl_xor_sync(0xffffffffu, v, 4);
                v += __shfl_xor_sync(0xffffffffu, v, 8);
                v += __shfl_xor_sync(0xffffffffu, v, 16);
                if (g == 0)
                    atomicAdd(&g_sall[colBase + wn * 64 + j * 8 + 2 * t + bb], v);
            }
    }
}

// ------- kernel 4 (fused): per-anchor finalize + last-block reduce ---------
__global__ void k_final_f(const void* __restrict__ lab, float* __restrict__ out) {
    __shared__ float ssum[256];
    __shared__ int   scnt[256];
    __shared__ int   s_last;
    int tid = threadIdx.x;
    int is64 = detect_is64(lab, tid);
    int i = blockIdx.x * 256 + tid;
    int c = is64 ? (int)((const long long*)lab)[i] : ((const int*)lab)[i];
    int m = g_cnt[c];
    int np = m - 1, nn = N - m;
    float sp = 0.0f;
    int ok = 0;
    if (np > 0 && nn > 0) {
        float sneg = g_sall[i] - g_samesum[i];
        sneg = fmaxf(sneg, 1e-30f);
        float x = g_lsep[i] + logf((float)nn) + logf(sneg) + logf((float)np);
        sp = (x > 0.0f) ? (x + log1pf(__expf(-x))) : log1pf(__expf(x));
        ok = 1;
    }
    ssum[tid] = sp; scnt[tid] = ok;
    __syncthreads();
    #pragma unroll
    for (int s = 128; s > 0; s >>= 1) {
        if (tid < s) { ssum[tid] += ssum[tid + s]; scnt[tid] += scnt[tid + s]; }
        __syncthreads();
    }
    if (tid == 0) {
        g_part[blockIdx.x] = ssum[0];
        g_pcnt[blockIdx.x] = scnt[0];
        __threadfence();
        unsigned v = atomicAdd(&g_done, 1u);
        s_last = (v == 31u);
    }
    __syncthreads();
    if (s_last) {
        if (tid < 32) {
            float v = *((volatile float*)&g_part[tid]);
            int   cc = *((volatile int*)&g_pcnt[tid]);
            #pragma unroll
            for (int k = 16; k >= 1; k >>= 1) {
                v  += __shfl_xor_sync(0xffffffffu, v, k);
                cc += __shfl_xor_sync(0xffffffffu, cc, k);
            }
            if (tid == 0) {
                out[0] = v / fmaxf((float)cc, 1.0f);
                g_done = 0;
            }
        }
        // re-zero g_cnt for the next deterministic run
        for (int q = tid; q < NC; q += 256) g_cnt[q] = 0;
    }
}

// ---------------- launch ---------------------------------------------------
extern "C" void kernel_launch(void* const* d_in, const int* in_sizes, int n_in,
                              void* d_out, int out_size) {
    const float* embeds = (const float*)d_in[0];
    const void*  labels = d_in[1];
    float* out = (float*)d_out;
    (void)in_sizes; (void)n_in; (void)out_size;

    cudaFuncSetAttribute(k_main_f, cudaFuncAttributeMaxDynamicSharedMemorySize, SMEM_SZ);

    k_norm<<<N / 8, 256>>>(embeds, labels);
    k_main_f<<<NBLK, 256, SMEM_SZ>>>();
    k_final_f<<<32, 256>>>(labels, out);
}